// round 12
// baseline (speedup 1.0000x reference)
#include <cuda_runtime.h>
#include <math.h>

#define LL 4096
#define FF 36
#define MM 100
#define HID 64
#define NEG_INF_V (-1e9f)

#define TI 8                     // i-values per k_main block
#define ROWS_T (TI + MM)         // 108 tile rows
#define ROWW 76                  // padded row width in floats (72 data + 4 pad); 304 B = 19*16

typedef unsigned long long u64;

// ---------------- device scratch ----------------
__device__ __align__(128) float g_P[(LL + 1) * 2 * FF];     // interleaved (S, S2)
__device__ float  g_kc;                 // c * log2(e)
__device__ float  g_ikc;                // 1 / (c * log2(e))
__device__ float4 g_ltab[MM];           // (1/l, l/500, log(l+1e-6)/6, 0)
__device__ float  g_bp[HID];            // sorted relu breakpoints
__device__ float2 g_ab[HID + 1];        // (slope, intercept) per bin

// ---------------- helpers ----------------
__device__ __forceinline__ float ex2(float x) {
    float y; asm("ex2.approx.ftz.f32 %0, %1;" : "=f"(y) : "f"(x)); return y;
}
__device__ __forceinline__ u64 pk(float lo, float hi) {
    u64 r; asm("mov.b64 %0, {%1,%2};" : "=l"(r) : "f"(lo), "f"(hi)); return r;
}
__device__ __forceinline__ void upk(u64 v, float& lo, float& hi) {
    asm("mov.b64 {%0,%1}, %2;" : "=f"(lo), "=f"(hi) : "l"(v));
}
__device__ __forceinline__ u64 fma2(u64 a, u64 b, u64 c) {
    u64 d; asm("fma.rn.f32x2 %0, %1, %2, %3;" : "=l"(d) : "l"(a), "l"(b), "l"(c)); return d;
}
__device__ __forceinline__ u64 mul2(u64 a, u64 b) {
    u64 d; asm("mul.rn.f32x2 %0, %1, %2;" : "=l"(d) : "l"(a), "l"(b)); return d;
}
// 16-byte shared load straight into two packed u64 (no pk MOVs)
__device__ __forceinline__ void lds2(u64& a, u64& b, unsigned addr) {
    asm("ld.shared.v2.b64 {%0,%1}, [%2];" : "=l"(a), "=l"(b) : "r"(addr));
}

// ---------------- k1: ONE kernel for scan + prep ----------------
__global__ __launch_bounds__(256) void k_scan_all(
        const float* __restrict__ x,
        const float* __restrict__ wf, const float* __restrict__ q,
        const float* __restrict__ w1, const float* __restrict__ b1,
        const float* __restrict__ w2, const float* __restrict__ b2) {
    __shared__ float wS[8], wS2[8];
    __shared__ float stb[HID], sdA[HID], sdB[HID];
    __shared__ float ssA[HID], ssB[HID];
    __shared__ float redA[HID], redB[HID];
    __shared__ float sA0B0[2];
    int t = threadIdx.x;

    if (blockIdx.x == FF) {   // ---- prep block ----
        if (t < HID) {
            float vh = 0.f;
            #pragma unroll
            for (int a = 0; a < 32; a++) vh = fmaf(wf[a], w1[a * HID + t], vh);
            float bh = b1[t], wh = w2[t];
            float tb, dA, dB, cA0 = 0.f, cB0 = 0.f;
            if (vh > 0.f)      { tb = -bh / vh; dA =  wh * vh; dB =  wh * bh; }
            else if (vh < 0.f) { tb = -bh / vh; dA = -wh * vh; dB = -wh * bh;
                                 cA0 = wh * vh; cB0 = wh * bh; }
            else               { tb = 3e38f; dA = 0.f; dB = 0.f;
                                 cB0 = wh * fmaxf(bh, 0.f); }
            stb[t] = tb; sdA[t] = dA; sdB[t] = dB;
            redA[t] = cA0; redB[t] = cB0;
        }
        if (t == 0) {
            float c = 0.f;
            #pragma unroll
            for (int a = 0; a < 32; a++) c = fmaf(wf[a], q[a], c);
            if (fabsf(c) < 1e-30f) c = 1e-30f;   // degenerate guard
            float kk = c * 1.4426950408889634f;
            g_kc = kk;
            g_ikc = 1.0f / kk;
        }
        if (t < MM) {
            float lf = (float)(t + 1);
            float4 v;
            v.x = 1.0f / lf;
            v.y = lf * (1.0f / 500.0f);
            v.z = logf(lf + 1e-6f) * (1.0f / 6.0f);
            v.w = 0.f;
            g_ltab[t] = v;
        }
        __syncthreads();
        if (t == 0) {
            float A0 = 0.f, B0 = b2[0];
            #pragma unroll
            for (int h = 0; h < HID; h++) { A0 += redA[h]; B0 += redB[h]; }
            sA0B0[0] = A0; sA0B0[1] = B0;
        }
        if (t < HID) {   // stable rank sort + scatter
            float tb = stb[t];
            int rank = 0;
            #pragma unroll
            for (int k = 0; k < HID; k++) {
                float o = stb[k];
                rank += (o < tb) || (o == tb && k < t);
            }
            ssA[rank] = sdA[t]; ssB[rank] = sdB[t];
            g_bp[rank] = tb;
        }
        __syncthreads();
        if (t <= HID) {
            float A = sA0B0[0], B = sA0B0[1];
            for (int k = 0; k < t; k++) { A += ssA[k]; B += ssB[k]; }
            g_ab[t] = make_float2(A, B);
        }
        return;
    }

    // ---- feature-column scan block ----
    int f = blockIdx.x;
    int lane = t & 31, wid = t >> 5;

    float v[16];
    const float* p = x + (size_t)t * 16 * FF + f;
    #pragma unroll
    for (int r = 0; r < 16; r++) v[r] = p[r * FF];

    float ts = 0.f, ts2 = 0.f;
    #pragma unroll
    for (int r = 0; r < 16; r++) { ts += v[r]; ts2 = fmaf(v[r], v[r], ts2); }

    float is = ts, is2 = ts2;
    #pragma unroll
    for (int d = 1; d < 32; d <<= 1) {
        float a = __shfl_up_sync(~0u, is, d);
        float b = __shfl_up_sync(~0u, is2, d);
        if (lane >= d) { is += a; is2 += b; }
    }
    if (lane == 31) { wS[wid] = is; wS2[wid] = is2; }
    __syncthreads();
    float off = 0.f, off2 = 0.f;
    #pragma unroll
    for (int w = 0; w < 8; w++)
        if (w < wid) { off += wS[w]; off2 += wS2[w]; }
    float s  = off  + is  - ts;    // exclusive prefix for this thread
    float s2 = off2 + is2 - ts2;

    if (t == 0) ((float2*)g_P)[f] = make_float2(0.f, 0.f);   // row 0
    float2* o = (float2*)g_P + f;
    int row0 = t * 16 + 1;
    #pragma unroll
    for (int r = 0; r < 16; r++) {
        float vv = v[r];
        s += vv; s2 = fmaf(vv, vv, s2);
        o[(size_t)(row0 + r) * FF] = make_float2(s, s2);
    }
}

// ---------------- k2: main — arg-space online softmax, packed shared loads ----------------
__global__ __launch_bounds__(256, 4) void k_main(float* __restrict__ out) {
    __shared__ __align__(16) float sh[ROWS_T * ROWW];
    __shared__ float4 s_lt[MM];
    __shared__ float  s_bp[HID];
    __shared__ float2 s_ab[HID + 1];
    __shared__ float  s_kc, s_ikc;
    int t = threadIdx.x;
    int i0 = blockIdx.x * TI;

    if (t < MM)       s_lt[t] = g_ltab[t];
    if (t < HID)      s_bp[t] = g_bp[t];
    if (t < HID + 1)  s_ab[t] = g_ab[t];
    if (t == 0)       { s_kc = g_kc; s_ikc = g_ikc; }

    {   // stage tile rows [i0, i0+ROWS_T) of g_P into padded shared rows
        int nrows = min(ROWS_T, LL + 1 - i0);
        int total = nrows * 18;
        const float4* src = (const float4*)(g_P + (size_t)i0 * 2 * FF);
        for (int idx = t; idx < total; idx += 256) {
            int r = idx / 18, c = idx % 18;
            *(float4*)&sh[r * ROWW + c * 4] = src[r * 18 + c];
        }
    }
    __syncthreads();

    unsigned sbase = (unsigned)__cvta_generic_to_shared(sh);
    float kc  = s_kc;
    float ikc = s_ikc;

    #pragma unroll 1
    for (int c = t; c < TI * MM; c += 256) {
        int li  = c / MM;
        int lm1 = c - li * MM;
        int l   = lm1 + 1;
        int gout = i0 * MM + c;
        if (i0 + li + l > LL) { out[gout] = NEG_INF_V; continue; }

        float4 lt  = s_lt[lm1];
        float invl = lt.x, lenf = lt.y, llf = lt.z;

        unsigned pe_a = sbase + (unsigned)((li + l) * (ROWW * 4));
        unsigned pi_a = sbase + (unsigned)(li * (ROWW * 4));

        float c1 = kc * invl;          // arg scale: u_mean = c1*dS, t = c1*dQ
        u64 c12 = pk(c1, c1);
        const u64 NEG1 = 0xBF800000BF800000ULL;

        // init from the two length features (arg space)
        float aL = kc * lenf, aG = kc * llf;
        float m = fmaxf(aL, aG);
        float eI0 = ex2(aL - m), eI1 = ex2(aG - m);
        float den0 = eI0, den1 = eI1;
        float num0 = aL * eI0, num1 = aG * eI1;

        #pragma unroll
        for (int grp = 0; grp < 6; grp++) {      // 12 args per group
            float u[12];
            #pragma unroll
            for (int k = 0; k < 3; k++) {
                int j = grp * 3 + k;
                u64 ea, eb, ia, ib;
                lds2(ea, eb, pe_a + j * 16);
                lds2(ia, ib, pi_a + j * 16);
                u64 d0 = fma2(ia, NEG1, ea);     // (dS, dQ) packed
                u64 d1 = fma2(ib, NEG1, eb);
                u64 w0 = mul2(d0, c12);          // (u_mean, c1*dQ)
                u64 w1 = mul2(d1, c12);
                float um0, t0, um1, t1;
                upk(w0, um0, t0); upk(w1, um1, t1);
                u[4 * k + 0] = um0;
                u[4 * k + 1] = fmaf(-(um0 * ikc), um0, t0);   // u_var = c1*dQ - u_mean^2/kc
                u[4 * k + 2] = um1;
                u[4 * k + 3] = fmaf(-(um1 * ikc), um1, t1);
            }
            // group max (tree) + single rescale
            float x0 = fmaxf(u[0], u[1]),  x1 = fmaxf(u[2], u[3]);
            float x2 = fmaxf(u[4], u[5]),  x3 = fmaxf(u[6], u[7]);
            float x4 = fmaxf(u[8], u[9]),  x5 = fmaxf(u[10], u[11]);
            x0 = fmaxf(x0, x1); x2 = fmaxf(x2, x3); x4 = fmaxf(x4, x5);
            float mn = fmaxf(m, fmaxf(fmaxf(x0, x2), x4));
            float sc = ex2(m - mn);
            m = mn;
            den0 *= sc; den1 *= sc; num0 *= sc; num1 *= sc;
            #pragma unroll
            for (int k = 0; k < 12; k += 2) {
                float e0 = ex2(u[k] - mn);
                float e1 = ex2(u[k + 1] - mn);
                den0 += e0; num0 = fmaf(u[k],     e0, num0);
                den1 += e1; num1 = fmaf(u[k + 1], e1, num1);
            }
        }

        float s = __fdividef(num0 + num1, den0 + den1) * ikc;

        // rank of s among sorted breakpoints (branchless)
        int lo = 0;
        #pragma unroll
        for (int st = 64; st > 0; st >>= 1) {
            int nx = lo + st;
            if (nx <= HID && s >= s_bp[nx - 1]) lo = nx;
        }
        float2 ab = s_ab[lo];
        out[gout] = fmaf(ab.x, s, ab.y);
    }
}

// ---------------- launch ----------------
extern "C" void kernel_launch(void* const* d_in, const int* in_sizes, int n_in,
                              void* d_out, int out_size) {
    const float* x  = (const float*)d_in[0];
    const float* wf = (const float*)d_in[1];
    const float* q  = (const float*)d_in[2];
    const float* w1 = (const float*)d_in[3];
    const float* b1 = (const float*)d_in[4];
    const float* w2 = (const float*)d_in[5];
    const float* b2 = (const float*)d_in[6];
    float* out = (float*)d_out;

    k_scan_all<<<FF + 1, 256>>>(x, wf, q, w1, b1, w2, b2);
    k_main<<<LL / TI, 256>>>(out);
}

// round 13
// speedup vs baseline: 1.0703x; 1.0703x over previous
#include <cuda_runtime.h>
#include <math.h>

#define LL 4096
#define FF 36
#define MM 100
#define HID 64
#define NEG_INF_V (-1e9f)

#define TI 8                     // i-values per k_main block
#define ROWS_T (TI + MM)         // 108 tile rows
#define ROWW 76                  // padded row width in floats (72 data + 4 pad); 304 B

typedef unsigned long long u64;

// ---------------- device scratch ----------------
__device__ __align__(128) float g_P[(LL + 1) * 2 * FF];     // interleaved (S, S2)
__device__ float  g_kc;                 // c * log2(e)
__device__ float  g_ikc;                // 1 / (c * log2(e))
__device__ float4 g_ltab[MM];           // (1/l, l/500, log(l+1e-6)/6, 0)
__device__ float  g_bp[HID];            // sorted relu breakpoints
__device__ float2 g_ab[HID + 1];        // (slope, intercept) per bin

// ---------------- helpers ----------------
__device__ __forceinline__ float ex2(float x) {
    float y; asm("ex2.approx.ftz.f32 %0, %1;" : "=f"(y) : "f"(x)); return y;
}
__device__ __forceinline__ u64 pk(float lo, float hi) {
    u64 r; asm("mov.b64 %0, {%1,%2};" : "=l"(r) : "f"(lo), "f"(hi)); return r;
}
__device__ __forceinline__ void upk(u64 v, float& lo, float& hi) {
    asm("mov.b64 {%0,%1}, %2;" : "=f"(lo), "=f"(hi) : "l"(v));
}
__device__ __forceinline__ u64 fma2(u64 a, u64 b, u64 c) {
    u64 d; asm("fma.rn.f32x2 %0, %1, %2, %3;" : "=l"(d) : "l"(a), "l"(b), "l"(c)); return d;
}
__device__ __forceinline__ u64 mul2(u64 a, u64 b) {
    u64 d; asm("mul.rn.f32x2 %0, %1, %2;" : "=l"(d) : "l"(a), "l"(b)); return d;
}
__device__ __forceinline__ void lds2(u64& a, u64& b, unsigned addr) {
    asm("ld.shared.v2.b64 {%0,%1}, [%2];" : "=l"(a), "=l"(b) : "r"(addr));
}

// ---------------- k1: ONE kernel for scan + prep ----------------
__global__ __launch_bounds__(256) void k_scan_all(
        const float* __restrict__ x,
        const float* __restrict__ wf, const float* __restrict__ q,
        const float* __restrict__ w1, const float* __restrict__ b1,
        const float* __restrict__ w2, const float* __restrict__ b2) {
    __shared__ float wS[8], wS2[8];
    __shared__ float stb[HID], sdA[HID], sdB[HID];
    __shared__ float ssA[HID], ssB[HID];
    __shared__ float redA[HID], redB[HID];
    __shared__ float sA0B0[2];
    int t = threadIdx.x;

    if (blockIdx.x == FF) {   // ---- prep block ----
        if (t < HID) {
            float vh = 0.f;
            #pragma unroll
            for (int a = 0; a < 32; a++) vh = fmaf(wf[a], w1[a * HID + t], vh);
            float bh = b1[t], wh = w2[t];
            float tb, dA, dB, cA0 = 0.f, cB0 = 0.f;
            if (vh > 0.f)      { tb = -bh / vh; dA =  wh * vh; dB =  wh * bh; }
            else if (vh < 0.f) { tb = -bh / vh; dA = -wh * vh; dB = -wh * bh;
                                 cA0 = wh * vh; cB0 = wh * bh; }
            else               { tb = 3e38f; dA = 0.f; dB = 0.f;
                                 cB0 = wh * fmaxf(bh, 0.f); }
            stb[t] = tb; sdA[t] = dA; sdB[t] = dB;
            redA[t] = cA0; redB[t] = cB0;
        }
        if (t == 0) {
            float c = 0.f;
            #pragma unroll
            for (int a = 0; a < 32; a++) c = fmaf(wf[a], q[a], c);
            if (fabsf(c) < 1e-30f) c = 1e-30f;   // degenerate guard
            float kk = c * 1.4426950408889634f;
            g_kc = kk;
            g_ikc = 1.0f / kk;
        }
        if (t < MM) {
            float lf = (float)(t + 1);
            float4 v;
            v.x = 1.0f / lf;
            v.y = lf * (1.0f / 500.0f);
            v.z = logf(lf + 1e-6f) * (1.0f / 6.0f);
            v.w = 0.f;
            g_ltab[t] = v;
        }
        __syncthreads();
        if (t == 0) {
            float A0 = 0.f, B0 = b2[0];
            #pragma unroll
            for (int h = 0; h < HID; h++) { A0 += redA[h]; B0 += redB[h]; }
            sA0B0[0] = A0; sA0B0[1] = B0;
        }
        if (t < HID) {   // stable rank sort + scatter
            float tb = stb[t];
            int rank = 0;
            #pragma unroll
            for (int k = 0; k < HID; k++) {
                float o = stb[k];
                rank += (o < tb) || (o == tb && k < t);
            }
            ssA[rank] = sdA[t]; ssB[rank] = sdB[t];
            g_bp[rank] = tb;
        }
        __syncthreads();
        if (t <= HID) {
            float A = sA0B0[0], B = sA0B0[1];
            for (int k = 0; k < t; k++) { A += ssA[k]; B += ssB[k]; }
            g_ab[t] = make_float2(A, B);
        }
        return;
    }

    // ---- feature-column scan block ----
    int f = blockIdx.x;
    int lane = t & 31, wid = t >> 5;

    float v[16];
    const float* p = x + (size_t)t * 16 * FF + f;
    #pragma unroll
    for (int r = 0; r < 16; r++) v[r] = p[r * FF];

    float ts = 0.f, ts2 = 0.f;
    #pragma unroll
    for (int r = 0; r < 16; r++) { ts += v[r]; ts2 = fmaf(v[r], v[r], ts2); }

    float is = ts, is2 = ts2;
    #pragma unroll
    for (int d = 1; d < 32; d <<= 1) {
        float a = __shfl_up_sync(~0u, is, d);
        float b = __shfl_up_sync(~0u, is2, d);
        if (lane >= d) { is += a; is2 += b; }
    }
    if (lane == 31) { wS[wid] = is; wS2[wid] = is2; }
    __syncthreads();
    float off = 0.f, off2 = 0.f;
    #pragma unroll
    for (int w = 0; w < 8; w++)
        if (w < wid) { off += wS[w]; off2 += wS2[w]; }
    float s  = off  + is  - ts;    // exclusive prefix for this thread
    float s2 = off2 + is2 - ts2;

    if (t == 0) ((float2*)g_P)[f] = make_float2(0.f, 0.f);   // row 0
    float2* o = (float2*)g_P + f;
    int row0 = t * 16 + 1;
    #pragma unroll
    for (int r = 0; r < 16; r++) {
        float vv = v[r];
        s += vv; s2 = fmaf(vv, vv, s2);
        o[(size_t)(row0 + r) * FF] = make_float2(s, s2);
    }
}

// ---------------- k2: main — fixed-shift softmax, fully parallel exp terms ----------------
__global__ __launch_bounds__(256, 4) void k_main(float* __restrict__ out) {
    __shared__ __align__(16) float sh[ROWS_T * ROWW];
    __shared__ float4 s_lt[MM];
    __shared__ float  s_bp[HID];
    __shared__ float2 s_ab[HID + 1];
    __shared__ float  s_kc, s_ikc;
    int t = threadIdx.x;
    int i0 = blockIdx.x * TI;

    if (t < MM)       s_lt[t] = g_ltab[t];
    if (t < HID)      s_bp[t] = g_bp[t];
    if (t < HID + 1)  s_ab[t] = g_ab[t];
    if (t == 0)       { s_kc = g_kc; s_ikc = g_ikc; }

    {   // stage tile rows [i0, i0+ROWS_T) of g_P into padded shared rows
        int nrows = min(ROWS_T, LL + 1 - i0);
        int total = nrows * 18;
        const float4* src = (const float4*)(g_P + (size_t)i0 * 2 * FF);
        for (int idx = t; idx < total; idx += 256) {
            int r = idx / 18, c = idx % 18;
            *(float4*)&sh[r * ROWW + c * 4] = src[r * 18 + c];
        }
    }
    __syncthreads();

    unsigned sbase = (unsigned)__cvta_generic_to_shared(sh);
    float kc  = s_kc;
    float ikc = s_ikc;

    #pragma unroll 1
    for (int c = t; c < TI * MM; c += 256) {
        int li  = c / MM;
        int lm1 = c - li * MM;
        int l   = lm1 + 1;
        int gout = i0 * MM + c;
        if (i0 + li + l > LL) { out[gout] = NEG_INF_V; continue; }

        float4 lt  = s_lt[lm1];
        float invl = lt.x, lenf = lt.y, llf = lt.z;

        unsigned pe_a = sbase + (unsigned)((li + l) * (ROWW * 4));
        unsigned pi_a = sbase + (unsigned)(li * (ROWW * 4));

        float c1 = kc * invl;          // arg scale: u_mean = c1*dS, raw = c1*dQ
        u64 c12 = pk(c1, c1);
        const u64 NEG1 = 0xBF800000BF800000ULL;

        // fixed shift: anchor at aL (softmax shift-invariant)
        float aL = kc * lenf, aG = kc * llf;
        float den0 = 1.f,  num0 = aL;          // aL term: e = 1
        float eG = ex2(aG - aL);
        float den1 = eG,   num1 = aG * eG;
        float den2 = 0.f,  num2 = 0.f;
        float den3 = 0.f,  num3 = 0.f;

        #pragma unroll
        for (int grp = 0; grp < 6; grp++) {      // 12 args per group
            float u[12];
            #pragma unroll
            for (int k = 0; k < 3; k++) {
                int j = grp * 3 + k;
                u64 ea, eb, ia, ib;
                lds2(ea, eb, pe_a + j * 16);
                lds2(ia, ib, pi_a + j * 16);
                u64 d0 = fma2(ia, NEG1, ea);     // (dS, dQ) packed
                u64 d1 = fma2(ib, NEG1, eb);
                u64 w0 = mul2(d0, c12);          // (u_mean, c1*dQ)
                u64 w1 = mul2(d1, c12);
                float um0, t0, um1, t1;
                upk(w0, um0, t0); upk(w1, um1, t1);
                u[4 * k + 0] = um0;
                u[4 * k + 1] = fmaf(-(um0 * ikc), um0, t0);   // u_var
                u[4 * k + 2] = um1;
                u[4 * k + 3] = fmaf(-(um1 * ikc), um1, t1);
            }
            #pragma unroll
            for (int k = 0; k < 12; k += 4) {
                float e0 = ex2(u[k]     - aL);
                float e1 = ex2(u[k + 1] - aL);
                float e2 = ex2(u[k + 2] - aL);
                float e3 = ex2(u[k + 3] - aL);
                den0 += e0; num0 = fmaf(u[k],     e0, num0);
                den1 += e1; num1 = fmaf(u[k + 1], e1, num1);
                den2 += e2; num2 = fmaf(u[k + 2], e2, num2);
                den3 += e3; num3 = fmaf(u[k + 3], e3, num3);
            }
        }

        float s = __fdividef((num0 + num1) + (num2 + num3),
                             (den0 + den1) + (den2 + den3)) * ikc;

        // rank of s among sorted breakpoints (branchless)
        int lo = 0;
        #pragma unroll
        for (int st = 64; st > 0; st >>= 1) {
            int nx = lo + st;
            if (nx <= HID && s >= s_bp[nx - 1]) lo = nx;
        }
        float2 ab = s_ab[lo];
        out[gout] = fmaf(ab.x, s, ab.y);
    }
}

// ---------------- launch ----------------
extern "C" void kernel_launch(void* const* d_in, const int* in_sizes, int n_in,
                              void* d_out, int out_size) {
    const float* x  = (const float*)d_in[0];
    const float* wf = (const float*)d_in[1];
    const float* q  = (const float*)d_in[2];
    const float* w1 = (const float*)d_in[3];
    const float* b1 = (const float*)d_in[4];
    const float* w2 = (const float*)d_in[5];
    const float* b2 = (const float*)d_in[6];
    float* out = (float*)d_out;

    k_scan_all<<<FF + 1, 256>>>(x, wf, q, w1, b1, w2, b2);
    k_main<<<LL / TI, 256>>>(out);
}